// round 12
// baseline (speedup 1.0000x reference)
#include <cuda_runtime.h>
#include <cuda_bf16.h>
#include <math.h>
#include <stdint.h>

#define L_LEN 15872
#define NT64 248

// ---------------- device scratch ----------------
__device__ float g_cond[4 * 80 * L_LEN];
__device__ float g_res0[4 * 120 * L_LEN];
__device__ float g_res1[4 * 120 * L_LEN];
__device__ float g_skip[4 * 240 * L_LEN];
__device__ float g_h[4 * 256 * L_LEN];
__device__ float g_bg[16 * 240];

// fragment-major bf16 weights: per fragment (c2, mtile, j) -> 32 lanes x 16B (uint4)
__device__ __align__(16) __nv_bfloat16 g_W1f[16 * 30 * 16 * 2 * 32 * 8];
__device__ __align__(16) __nv_bfloat16 g_W2f[16 * 12 * 24 * 2 * 32 * 8];
__device__ __align__(16) __nv_bfloat16 g_WH1f[24 * 16 * 2 * 32 * 8];
__device__ __align__(16) __nv_bfloat16 g_WH2f[24 * 16 * 2 * 32 * 8];

// ---------------- helpers ----------------
__device__ __forceinline__ uint32_t smem_u32(const void* p) {
    uint32_t a;
    asm("{ .reg .u64 t; cvta.to.shared.u64 t, %1; cvt.u32.u64 %0, t; }" : "=r"(a) : "l"(p));
    return a;
}
__device__ __forceinline__ void ldmB(uint32_t* b, uint32_t addr) {
    asm volatile("ldmatrix.sync.aligned.m8n8.x4.shared.b16 {%0,%1,%2,%3}, [%4];"
        : "=r"(b[0]), "=r"(b[1]), "=r"(b[2]), "=r"(b[3]) : "r"(addr));
}
__device__ __forceinline__ void mma16816(float* c, const uint32_t* a, const uint32_t* b) {
    asm volatile("mma.sync.aligned.m16n8k16.row.col.f32.bf16.bf16.f32 "
        "{%0,%1,%2,%3}, {%4,%5,%6,%7}, {%8,%9}, {%0,%1,%2,%3};"
        : "+f"(c[0]), "+f"(c[1]), "+f"(c[2]), "+f"(c[3])
        : "r"(a[0]), "r"(a[1]), "r"(a[2]), "r"(a[3]), "r"(b[0]), "r"(b[1]));
}
__device__ __forceinline__ __nv_bfloat16 bsel(float v, int term) {
    __nv_bfloat16 h = __float2bfloat16(v);
    if (term < 2) return h;
    return __float2bfloat16(v - __bfloat162float(h));
}
__device__ __forceinline__ float sigmoidf_(float g) {
    return __fdividef(1.f, 1.f + __expf(-g));
}
__device__ __forceinline__ float tanhf_acc(float f) {
    f = fminf(15.f, fmaxf(-15.f, f));
    float e = expm1f(2.f * f);
    return __fdividef(e, e + 2.f);
}

// ---------------- weight prep (fragment-major) ----------------
__global__ void prep_kernel(const float* __restrict__ w_gate, const float* __restrict__ b_gate,
                            const float* __restrict__ w_cond, const float* __restrict__ b_cond,
                            const float* __restrict__ w_res,  const float* __restrict__ w_skip,
                            const float* __restrict__ w_h1,   const float* __restrict__ w_h2)
{
    const int NW1 = 16 * 245760;
    const int NW2 = 16 * 147456;
    const int NH  = 196608;
    const int total = NW1 + NW2 + 2 * NH + 16 * 240;
    for (int idx = blockIdx.x * blockDim.x + threadIdx.x; idx < total;
         idx += gridDim.x * blockDim.x) {
        int i = idx;
        if (i < NW1) {
            int blk = i / 245760, q = i % 245760;
            int c2 = q / 8192;  q %= 8192;
            int mt = q / 512;   q %= 512;
            int j  = q / 256;   q %= 256;
            int lane = q / 8;   int e = q % 8;
            int r4 = e >> 1, h = e & 1;
            int kk = j * 16 + (r4 & 2) * 4 + (lane & 3) * 2 + h;
            int k = (c2 % 10) * 32 + kk, term = c2 / 10;
            int chf = (mt << 3) + (lane >> 2);
            float v = 0.f;
            if (chf < 120) {
                int gch = ((r4 & 1) == 0) ? chf : 120 + chf;
                if (k < 120)       v = w_gate[((blk * 240 + gch) * 120 + k) * 2];
                else if (k < 240)  v = w_gate[((blk * 240 + gch) * 120 + (k - 120)) * 2 + 1];
                else               v = w_cond[(blk * 240 + gch) * 80 + (k - 240)];
            }
            g_W1f[i] = bsel(v, term);
        } else if ((i -= NW1) < NW2) {
            int blk = i / 147456, q = i % 147456;
            int c2 = q / 12288; q %= 12288;
            int mt = q / 512;   q %= 512;
            int j  = q / 256;   q %= 256;
            int lane = q / 8;   int e = q % 8;
            int r4 = e >> 1, h = e & 1;
            int row = mt * 16 + (r4 & 1) * 8 + (lane >> 2);
            int kk = j * 16 + (r4 & 2) * 4 + (lane & 3) * 2 + h;
            int k = (c2 % 4) * 32 + kk, term = c2 / 4;
            float v = 0.f;
            if (k < 120) {
                if (row < 240)                    v = w_skip[(blk * 240 + row) * 120 + k];
                else if (row >= 256 && row < 376) v = w_res[(blk * 120 + (row - 256)) * 120 + k];
            }
            g_W2f[i] = bsel(v, term);
        } else if ((i -= NW2) < 2 * NH) {
            int which = i / NH;
            int q = i % NH;
            int c2 = q / 8192;  q %= 8192;
            int mt = q / 512;   q %= 512;
            int j  = q / 256;   q %= 256;
            int lane = q / 8;   int e = q % 8;
            int r4 = e >> 1, h = e & 1;
            int row = mt * 16 + (r4 & 1) * 8 + (lane >> 2);
            int kk = j * 16 + (r4 & 2) * 4 + (lane & 3) * 2 + h;
            int k = (c2 % 8) * 32 + kk, term = c2 / 8;
            float v;
            if (which == 0) v = (k < 240) ? w_h1[row * 240 + k] : 0.f;
            else            v = w_h2[row * 256 + k];
            (which == 0 ? g_WH1f : g_WH2f)[i % NH] = bsel(v, term);
        } else {
            i -= 2 * NH;
            g_bg[i] = b_gate[i] + b_cond[i];
        }
    }
}

// ---------------- residual init ----------------
__global__ void init_kernel(const float* __restrict__ wav, const float* __restrict__ w_in,
                            const float* __restrict__ b_in)
{
    const int total = 4 * 120 * L_LEN;
    for (int idx = blockIdx.x * blockDim.x + threadIdx.x; idx < total;
         idx += gridDim.x * blockDim.x) {
        int t = idx % L_LEN;
        int br = idx / L_LEN;
        int r = br % 120, b = br / 120;
        g_res0[idx] = w_in[r] * wav[b * L_LEN + t] + b_in[r];
    }
}

// ---------------- mel upsample (fp32) ----------------
extern __shared__ char dynsmem[];

__global__ void __launch_bounds__(256) upsample_kernel(const float* __restrict__ mel,
                                                       const float* __restrict__ w_up,
                                                       const float* __restrict__ b_up)
{
    float* mel_s = (float*)dynsmem;
    float* ws    = (float*)dynsmem + 4 * 80 * 68;
    const int p = blockIdx.x, tid = threadIdx.x;

    for (int idx = tid; idx < 4 * 80 * 68; idx += 256) mel_s[idx] = 0.f;
    __syncthreads();
    for (int idx = tid; idx < 4 * 80 * 63; idx += 256)
        mel_s[(idx / 63) * 68 + (idx % 63) + 1] = mel[idx];
    bool valid[4];
#pragma unroll
    for (int v = 0; v < 4; v++) {
        int kk = 400 + p + 256 * (v - 2);
        valid[v] = (kk >= 0) && (kk < 800);
        if (valid[v])
            for (int idx = tid; idx < 6400; idx += 256)
                ws[(v * 80 + idx / 80) * 80 + idx % 80] = w_up[((idx / 80) * 80 + idx % 80) * 800 + kk];
    }
    __syncthreads();

    for (int tile = tid; tile < 320; tile += 256) {
        int og = tile >> 5, b = (tile >> 3) & 3, ug = tile & 7;
        int o0 = og * 8, u0 = ug * 8;
        float acc[8][8];
#pragma unroll
        for (int a = 0; a < 8; a++)
#pragma unroll
            for (int c = 0; c < 8; c++) acc[a][c] = 0.f;
        const float* msb = mel_s + b * 80 * 68;
#pragma unroll
        for (int v = 0; v < 4; v++) {
            if (!valid[v]) continue;
            int vv = v - 2;
#pragma unroll 4
            for (int m = 0; m < 80; m++) {
                const float* wr = ws + (v * 80 + m) * 80 + o0;
                float4 wA = *(const float4*)wr;
                float4 wB = *(const float4*)(wr + 4);
                float wv[8] = {wA.x, wA.y, wA.z, wA.w, wB.x, wB.y, wB.z, wB.w};
                const float* xr = msb + m * 68 + (u0 - vv) + 1;
                float xv[8];
#pragma unroll
                for (int c = 0; c < 8; c++) xv[c] = xr[c];
#pragma unroll
                for (int a = 0; a < 8; a++)
#pragma unroll
                    for (int c = 0; c < 8; c++)
                        acc[a][c] = fmaf(wv[a], xv[c], acc[a][c]);
            }
        }
#pragma unroll
        for (int a = 0; a < 8; a++) {
            float bo = b_up[o0 + a];
#pragma unroll
            for (int c = 0; c < 8; c++)
                if (u0 + c < 62)
                    g_cond[((size_t)b * 80 + o0 + a) * L_LEN + 256 * (u0 + c) + p] = acc[a][c] + bo;
        }
    }
}

// ---------------- fused residual block (mma.sync, batched LDSM) ----------------
#define XHI 0
#define XLO 44032
#define ZHI 88064
#define ZLO 105472
#define SMEM_BLOCK 122880

__global__ void __launch_bounds__(512, 1) block_kernel(const float* __restrict__ bsk_all,
                                                       const float* __restrict__ brs_all,
                                                       int blk, int d, int first, int parity)
{
    char* smb = dynsmem;
    const uint32_t su = smem_u32(smb);
    const int tid = threadIdx.x, w = tid >> 5, lane = tid & 31;
    const int wr = w >> 1, wt = w & 1;
    const int b = blockIdx.y, t0 = blockIdx.x << 6;

    const float* res_in  = (parity ? g_res1 : g_res0) + (size_t)b * 120 * L_LEN;
    float*       res_out = (parity ? g_res0 : g_res1) + (size_t)b * 120 * L_LEN;
    const float* condb   = g_cond + (size_t)b * 80 * L_LEN;

    const uint4* A1 = ((const uint4*)g_W1f) + (size_t)blk * (30 * 16 * 2 * 32);
    const uint4* A2 = ((const uint4*)g_W2f) + (size_t)blk * (12 * 24 * 2 * 32);

    // stage X: [64t][320k] fp32 -> bf16 hi/lo
    __nv_bfloat16* xh = (__nv_bfloat16*)(smb + XHI);
    __nv_bfloat16* xl = (__nv_bfloat16*)(smb + XLO);
    for (int idx = tid; idx < 320 * 64; idx += 512) {
        int t = idx & 63, k = idx >> 6;
        float v;
        if (k < 120)      { int ts = t0 + t - d; v = (ts >= 0) ? res_in[k * L_LEN + ts] : 0.f; }
        else if (k < 240)   v = res_in[(k - 120) * L_LEN + t0 + t];
        else                v = condb[(k - 240) * L_LEN + t0 + t];
        __nv_bfloat16 h = __float2bfloat16(v);
        xh[t * 344 + k] = h;
        xl[t * 344 + k] = __float2bfloat16(v - __bfloat162float(h));
    }
    __syncthreads();

    float acc[2][4][4];
#pragma unroll
    for (int m = 0; m < 2; m++)
#pragma unroll
        for (int n = 0; n < 4; n++)
#pragma unroll
            for (int q = 0; q < 4; q++) acc[m][n][q] = 0.f;

    const int brow = ((lane & 16) >> 1) + (lane & 7);
    // per-warp smem row base for B loads (t rows)
    const uint32_t browoff0 = (uint32_t)(((wt << 5) + brow) * 344 * 2);
    const uint32_t browoff1 = (uint32_t)(((wt << 5) + 16 + brow) * 344 * 2);

    // GEMM1: register-double-buffered A fragments from L2, batched LDSMs, no barriers
    uint4 curA[2][2], nxtA[2][2];
#pragma unroll
    for (int m = 0; m < 2; m++)
#pragma unroll
        for (int j = 0; j < 2; j++)
            curA[m][j] = A1[(((2 * wr + m) * 2) + j) * 32 + lane];

    int kc = 0;
    for (int c2 = 0; c2 < 30; c2++) {
        if (c2 < 29) {
#pragma unroll
            for (int m = 0; m < 2; m++)
#pragma unroll
                for (int j = 0; j < 2; j++)
                    nxtA[m][j] = A1[((((c2 + 1) * 16 + (2 * wr + m)) * 2) + j) * 32 + lane];
        }
        const uint32_t xb = su + ((c2 >= 10 && c2 < 20) ? XLO : XHI);
        // all 4 B-fragment loads up front (one latency exposure)
        uint32_t bf[2][2][4];
        {
            const uint32_t cb = (uint32_t)(((kc << 5) + (lane & 8)) * 2);
            ldmB(bf[0][0], xb + browoff0 + cb);
            ldmB(bf[0][1], xb + browoff1 + cb);
            ldmB(bf[1][0], xb + browoff0 + cb + 32);
            ldmB(bf[1][1], xb + browoff1 + cb + 32);
        }
#pragma unroll
        for (int j = 0; j < 2; j++)
#pragma unroll
            for (int m = 0; m < 2; m++)
#pragma unroll
                for (int nt = 0; nt < 4; nt++)
                    mma16816(acc[m][nt], (const uint32_t*)&curA[m][j], &bf[j][nt >> 1][(nt & 1) << 1]);
#pragma unroll
        for (int m = 0; m < 2; m++)
#pragma unroll
            for (int j = 0; j < 2; j++)
                curA[m][j] = nxtA[m][j];
        if (++kc == 10) kc = 0;
    }

    // activation -> z (bf16 hi/lo) [64t][136ch]
    const float* bg = g_bg + blk * 240;
    __nv_bfloat16* zh = (__nv_bfloat16*)(smb + ZHI);
    __nv_bfloat16* zl = (__nv_bfloat16*)(smb + ZLO);
#pragma unroll
    for (int m = 0; m < 2; m++) {
        int mt = 2 * wr + m;
        int ch = (mt << 3) + (lane >> 2);
        bool valid = ch < 120;
        float bf_ = valid ? bg[ch] : 0.f;
        float bg_ = valid ? bg[120 + ch] : 0.f;
#pragma unroll
        for (int nt = 0; nt < 4; nt++) {
            int tt = (wt << 5) + (nt << 3) + ((lane & 3) << 1);
#pragma unroll
            for (int q = 0; q < 2; q++) {
                float z = 0.f;
                if (valid) {
                    float f = acc[m][nt][q] + bf_;
                    float g = acc[m][nt][2 + q] + bg_;
                    z = tanhf_acc(f) * sigmoidf_(g);
                }
                __nv_bfloat16 h = __float2bfloat16(z);
                zh[(tt + q) * 136 + ch] = h;
                zl[(tt + q) * 136 + ch] = __float2bfloat16(z - __bfloat162float(h));
            }
        }
    }
    __syncthreads();

    float ac2[3][4][4];
#pragma unroll
    for (int m = 0; m < 3; m++)
#pragma unroll
        for (int n = 0; n < 4; n++)
#pragma unroll
            for (int q = 0; q < 4; q++) ac2[m][n][q] = 0.f;

    const uint32_t zrow0 = (uint32_t)(((wt << 5) + brow) * 136 * 2);
    const uint32_t zrow1 = (uint32_t)(((wt << 5) + 16 + brow) * 136 * 2);

    // GEMM2: A fragments from L2 per chunk, batched LDSMs, no barriers
    for (int c2 = 0; c2 < 12; c2++) {
        uint4 a2[3][2];
#pragma unroll
        for (int m = 0; m < 3; m++)
#pragma unroll
            for (int j = 0; j < 2; j++)
                a2[m][j] = A2[(((c2 * 24 + (3 * wr + m)) * 2) + j) * 32 + lane];
        const uint32_t zb = su + (((c2 >> 2) == 1) ? ZLO : ZHI);
        uint32_t bf[2][2][4];
        {
            const uint32_t cb = (uint32_t)((((c2 & 3) << 5) + (lane & 8)) * 2);
            ldmB(bf[0][0], zb + zrow0 + cb);
            ldmB(bf[0][1], zb + zrow1 + cb);
            ldmB(bf[1][0], zb + zrow0 + cb + 32);
            ldmB(bf[1][1], zb + zrow1 + cb + 32);
        }
#pragma unroll
        for (int j = 0; j < 2; j++)
#pragma unroll
            for (int m = 0; m < 3; m++)
#pragma unroll
                for (int nt = 0; nt < 4; nt++)
                    mma16816(ac2[m][nt], (const uint32_t*)&a2[m][j], &bf[j][nt >> 1][(nt & 1) << 1]);
    }

    const float* bsk = bsk_all + blk * 240;
    const float* brs = brs_all + blk * 120;
    float* skipb = g_skip + (size_t)b * 240 * L_LEN;
#pragma unroll
    for (int m = 0; m < 3; m++) {
        int mt = 3 * wr + m;
#pragma unroll
        for (int h2 = 0; h2 < 2; h2++) {
            int row = (mt << 4) + (lane >> 2) + (h2 << 3);
#pragma unroll
            for (int nt = 0; nt < 4; nt++) {
                int tt = t0 + (wt << 5) + (nt << 3) + ((lane & 3) << 1);
                float v0 = ac2[m][nt][h2 << 1], v1 = ac2[m][nt][(h2 << 1) + 1];
                if (row < 240) {
                    size_t o = (size_t)row * L_LEN + tt;
                    float bb = bsk[row];
                    if (first) { skipb[o] = v0 + bb; skipb[o + 1] = v1 + bb; }
                    else       { skipb[o] += v0 + bb; skipb[o + 1] += v1 + bb; }
                } else if (row >= 256 && row < 376) {
                    int rc = row - 256;
                    size_t o = (size_t)rc * L_LEN + tt;
                    float bb = brs[rc];
                    res_out[o]     = res_in[o]     + v0 + bb;
                    res_out[o + 1] = res_in[o + 1] + v1 + bb;
                }
            }
        }
    }
}

// ---------------- head GEMM (mma.sync, batched LDSM) ----------------
#define HXHI 0
#define HXLO 33792
#define SMEM_HEAD 67584

__global__ void __launch_bounds__(512, 1) head_kernel(const float* __restrict__ bias,
                                                      float* __restrict__ outp, int which)
{
    char* smb = dynsmem;
    const uint32_t su = smem_u32(smb);
    const int tid = threadIdx.x, w = tid >> 5, lane = tid & 31;
    const int wr = w >> 1, wt = w & 1;
    const int b = blockIdx.y, t0 = blockIdx.x << 6;

    const int Kreal = which ? 256 : 240;
    const float* srcb = (which ? g_h : g_skip) + (size_t)b * Kreal * L_LEN;
    const uint4* A = (const uint4*)(which ? g_WH2f : g_WH1f);
    float* out = (which ? outp : g_h) + (size_t)b * 256 * L_LEN;

    __nv_bfloat16* xh = (__nv_bfloat16*)(smb + HXHI);
    __nv_bfloat16* xl = (__nv_bfloat16*)(smb + HXLO);
    for (int idx = tid; idx < 256 * 64; idx += 512) {
        int t = idx & 63, k = idx >> 6;
        float v = (k < Kreal) ? srcb[k * L_LEN + t0 + t] : 0.f;
        v = v > 0.f ? v : 0.f;
        __nv_bfloat16 h = __float2bfloat16(v);
        xh[t * 264 + k] = h;
        xl[t * 264 + k] = __float2bfloat16(v - __bfloat162float(h));
    }
    __syncthreads();

    float acc[2][4][4];
#pragma unroll
    for (int m = 0; m < 2; m++)
#pragma unroll
        for (int n = 0; n < 4; n++)
#pragma unroll
            for (int q = 0; q < 4; q++) acc[m][n][q] = 0.f;

    const int brow = ((lane & 16) >> 1) + (lane & 7);
    const uint32_t hrow0 = (uint32_t)(((wt << 5) + brow) * 264 * 2);
    const uint32_t hrow1 = (uint32_t)(((wt << 5) + 16 + brow) * 264 * 2);

    uint4 curA[2][2], nxtA[2][2];
#pragma unroll
    for (int m = 0; m < 2; m++)
#pragma unroll
        for (int j = 0; j < 2; j++)
            curA[m][j] = A[(((2 * wr + m) * 2) + j) * 32 + lane];

    for (int c2 = 0; c2 < 24; c2++) {
        if (c2 < 23) {
#pragma unroll
            for (int m = 0; m < 2; m++)
#pragma unroll
                for (int j = 0; j < 2; j++)
                    nxtA[m][j] = A[((((c2 + 1) * 16 + (2 * wr + m)) * 2) + j) * 32 + lane];
        }
        const uint32_t xb = su + ((c2 >= 8 && c2 < 16) ? HXLO : HXHI);
        uint32_t bf[2][2][4];
        {
            const uint32_t cb = (uint32_t)((((c2 & 7) << 5) + (lane & 8)) * 2);
            ldmB(bf[0][0], xb + hrow0 + cb);
            ldmB(bf[0][1], xb + hrow1 + cb);
            ldmB(bf[1][0], xb + hrow0 + cb + 32);
            ldmB(bf[1][1], xb + hrow1 + cb + 32);
        }
#pragma unroll
        for (int j = 0; j < 2; j++)
#pragma unroll
            for (int m = 0; m < 2; m++)
#pragma unroll
                for (int nt = 0; nt < 4; nt++)
                    mma16816(acc[m][nt], (const uint32_t*)&curA[m][j], &bf[j][nt >> 1][(nt & 1) << 1]);
#pragma unroll
        for (int m = 0; m < 2; m++)
#pragma unroll
            for (int j = 0; j < 2; j++)
                curA[m][j] = nxtA[m][j];
    }

#pragma unroll
    for (int m = 0; m < 2; m++) {
        int mt = 2 * wr + m;
#pragma unroll
        for (int h2 = 0; h2 < 2; h2++) {
            int ch = (mt << 4) + (lane >> 2) + (h2 << 3);
            float bb = bias[ch];
#pragma unroll
            for (int nt = 0; nt < 4; nt++) {
                int tt = t0 + (wt << 5) + (nt << 3) + ((lane & 3) << 1);
                size_t o = (size_t)ch * L_LEN + tt;
                out[o]     = acc[m][nt][h2 << 1] + bb;
                out[o + 1] = acc[m][nt][(h2 << 1) + 1] + bb;
            }
        }
    }
}

// ---------------- launcher ----------------
extern "C" void kernel_launch(void* const* d_in, const int* in_sizes, int n_in,
                              void* d_out, int out_size)
{
    const float* wav    = (const float*)d_in[0];
    const float* mel    = (const float*)d_in[1];
    const float* w_up   = (const float*)d_in[2];
    const float* b_up   = (const float*)d_in[3];
    const float* w_in   = (const float*)d_in[4];
    const float* b_in   = (const float*)d_in[5];
    const float* w_gate = (const float*)d_in[6];
    const float* b_gate = (const float*)d_in[7];
    const float* w_cond = (const float*)d_in[8];
    const float* b_cond = (const float*)d_in[9];
    const float* w_res  = (const float*)d_in[10];
    const float* b_res  = (const float*)d_in[11];
    const float* w_skip = (const float*)d_in[12];
    const float* b_skip = (const float*)d_in[13];
    const float* w_h1   = (const float*)d_in[14];
    const float* b_h1   = (const float*)d_in[15];
    const float* w_h2   = (const float*)d_in[16];
    const float* b_h2   = (const float*)d_in[17];
    float* out = (float*)d_out;

    const int SMEM_UP = (4 * 80 * 68 + 4 * 80 * 80) * 4;
    cudaFuncSetAttribute(block_kernel,    cudaFuncAttributeMaxDynamicSharedMemorySize, SMEM_BLOCK);
    cudaFuncSetAttribute(head_kernel,     cudaFuncAttributeMaxDynamicSharedMemorySize, SMEM_HEAD);
    cudaFuncSetAttribute(upsample_kernel, cudaFuncAttributeMaxDynamicSharedMemorySize, SMEM_UP);

    prep_kernel<<<4096, 256>>>(w_gate, b_gate, w_cond, b_cond, w_res, w_skip, w_h1, w_h2);
    upsample_kernel<<<256, 256, SMEM_UP>>>(mel, w_up, b_up);
    init_kernel<<<4096, 256>>>(wav, w_in, b_in);

    dim3 grid(NT64, 4);
    for (int i = 0; i < 16; i++)
        block_kernel<<<grid, 512, SMEM_BLOCK>>>(b_skip, b_res, i, 1 << (i & 7),
                                                (i == 0) ? 1 : 0, i & 1);

    head_kernel<<<grid, 512, SMEM_HEAD>>>(b_h1, out, 0);
    head_kernel<<<grid, 512, SMEM_HEAD>>>(b_h2, out, 1);
}

// round 14
// speedup vs baseline: 1.0128x; 1.0128x over previous
#include <cuda_runtime.h>
#include <cuda_fp16.h>
#include <math.h>
#include <stdint.h>

#define L_LEN 15872
#define NT64 248

// ---------------- device scratch ----------------
__device__ float g_cond[4 * 80 * L_LEN];
__device__ float g_res0[4 * 120 * L_LEN];
__device__ float g_res1[4 * 120 * L_LEN];
__device__ float g_skip[4 * 240 * L_LEN];
__device__ float g_h[4 * 256 * L_LEN];
__device__ float g_bg[16 * 240];

// fragment-major fp16 weights (2-term hi/lo in K): per fragment (c2, mtile, j) -> 32 lanes x 16B
__device__ __align__(16) __half g_W1f[16 * 20 * 16 * 2 * 32 * 8];   // 2621440
__device__ __align__(16) __half g_W2f[16 * 8 * 24 * 2 * 32 * 8];    // 1572864
__device__ __align__(16) __half g_WH1f[16 * 16 * 2 * 32 * 8];       // 131072
__device__ __align__(16) __half g_WH2f[16 * 16 * 2 * 32 * 8];

// ---------------- helpers ----------------
__device__ __forceinline__ uint32_t smem_u32(const void* p) {
    uint32_t a;
    asm("{ .reg .u64 t; cvta.to.shared.u64 t, %1; cvt.u32.u64 %0, t; }" : "=r"(a) : "l"(p));
    return a;
}
__device__ __forceinline__ void ldmB(uint32_t* b, uint32_t addr) {
    asm volatile("ldmatrix.sync.aligned.m8n8.x4.shared.b16 {%0,%1,%2,%3}, [%4];"
        : "=r"(b[0]), "=r"(b[1]), "=r"(b[2]), "=r"(b[3]) : "r"(addr));
}
__device__ __forceinline__ void mma16816(float* c, const uint32_t* a, const uint32_t* b) {
    asm volatile("mma.sync.aligned.m16n8k16.row.col.f32.f16.f16.f32 "
        "{%0,%1,%2,%3}, {%4,%5,%6,%7}, {%8,%9}, {%0,%1,%2,%3};"
        : "+f"(c[0]), "+f"(c[1]), "+f"(c[2]), "+f"(c[3])
        : "r"(a[0]), "r"(a[1]), "r"(a[2]), "r"(a[3]), "r"(b[0]), "r"(b[1]));
}
__device__ __forceinline__ __half hsel(float v, int term) {
    __half h = __float2half_rn(v);
    if (term == 0) return h;
    return __float2half_rn(v - __half2float(h));
}
__device__ __forceinline__ float sigmoidf_(float g) {
    return __fdividef(1.f, 1.f + __expf(-g));
}
__device__ __forceinline__ float tanhf_acc(float f) {
    f = fminf(15.f, fmaxf(-15.f, f));
    float e = expm1f(2.f * f);
    return __fdividef(e, e + 2.f);
}

// ---------------- weight prep (fragment-major, fp16 2-term) ----------------
__global__ void prep_kernel(const float* __restrict__ w_gate, const float* __restrict__ b_gate,
                            const float* __restrict__ w_cond, const float* __restrict__ b_cond,
                            const float* __restrict__ w_res,  const float* __restrict__ w_skip,
                            const float* __restrict__ w_h1,   const float* __restrict__ w_h2)
{
    const int NW1 = 16 * 163840;
    const int NW2 = 16 * 98304;
    const int NH  = 131072;
    const int total = NW1 + NW2 + 2 * NH + 16 * 240;
    for (int idx = blockIdx.x * blockDim.x + threadIdx.x; idx < total;
         idx += gridDim.x * blockDim.x) {
        int i = idx;
        if (i < NW1) {
            int blk = i / 163840, q = i % 163840;
            int c2 = q / 8192;  q %= 8192;       // 0..19
            int mt = q / 512;   q %= 512;
            int j  = q / 256;   q %= 256;
            int lane = q / 8;   int e = q % 8;
            int r4 = e >> 1, h = e & 1;
            int kk = j * 16 + (r4 & 2) * 4 + (lane & 3) * 2 + h;
            int k = (c2 % 10) * 32 + kk, term = c2 / 10;
            int chf = (mt << 3) + (lane >> 2);
            float v = 0.f;
            if (chf < 120) {
                int gch = ((r4 & 1) == 0) ? chf : 120 + chf;
                if (k < 120)       v = w_gate[((blk * 240 + gch) * 120 + k) * 2];
                else if (k < 240)  v = w_gate[((blk * 240 + gch) * 120 + (k - 120)) * 2 + 1];
                else               v = w_cond[(blk * 240 + gch) * 80 + (k - 240)];
            }
            g_W1f[i] = hsel(v, term);
        } else if ((i -= NW1) < NW2) {
            int blk = i / 98304, q = i % 98304;
            int c2 = q / 12288; q %= 12288;      // 0..7
            int mt = q / 512;   q %= 512;
            int j  = q / 256;   q %= 256;
            int lane = q / 8;   int e = q % 8;
            int r4 = e >> 1, h = e & 1;
            int row = mt * 16 + (r4 & 1) * 8 + (lane >> 2);
            int kk = j * 16 + (r4 & 2) * 4 + (lane & 3) * 2 + h;
            int k = (c2 % 4) * 32 + kk, term = c2 / 4;
            float v = 0.f;
            if (k < 120) {
                if (row < 240)                    v = w_skip[(blk * 240 + row) * 120 + k];
                else if (row >= 256 && row < 376) v = w_res[(blk * 120 + (row - 256)) * 120 + k];
            }
            g_W2f[i] = hsel(v, term);
        } else if ((i -= NW2) < 2 * NH) {
            int which = i / NH;
            int q = i % NH;
            int c2 = q / 8192;  q %= 8192;       // 0..15
            int mt = q / 512;   q %= 512;
            int j  = q / 256;   q %= 256;
            int lane = q / 8;   int e = q % 8;
            int r4 = e >> 1, h = e & 1;
            int row = mt * 16 + (r4 & 1) * 8 + (lane >> 2);
            int kk = j * 16 + (r4 & 2) * 4 + (lane & 3) * 2 + h;
            int k = (c2 % 8) * 32 + kk, term = c2 / 8;
            float v;
            if (which == 0) v = (k < 240) ? w_h1[row * 240 + k] : 0.f;
            else            v = w_h2[row * 256 + k];
            (which == 0 ? g_WH1f : g_WH2f)[i % NH] = hsel(v, term);
        } else {
            i -= 2 * NH;
            g_bg[i] = b_gate[i] + b_cond[i];
        }
    }
}

// ---------------- residual init ----------------
__global__ void init_kernel(const float* __restrict__ wav, const float* __restrict__ w_in,
                            const float* __restrict__ b_in)
{
    const int total = 4 * 120 * L_LEN;
    for (int idx = blockIdx.x * blockDim.x + threadIdx.x; idx < total;
         idx += gridDim.x * blockDim.x) {
        int t = idx % L_LEN;
        int br = idx / L_LEN;
        int r = br % 120, b = br / 120;
        g_res0[idx] = w_in[r] * wav[b * L_LEN + t] + b_in[r];
    }
}

// ---------------- mel upsample (fp32) ----------------
extern __shared__ char dynsmem[];

__global__ void __launch_bounds__(256) upsample_kernel(const float* __restrict__ mel,
                                                       const float* __restrict__ w_up,
                                                       const float* __restrict__ b_up)
{
    float* mel_s = (float*)dynsmem;
    float* ws    = (float*)dynsmem + 4 * 80 * 68;
    const int p = blockIdx.x, tid = threadIdx.x;

    for (int idx = tid; idx < 4 * 80 * 68; idx += 256) mel_s[idx] = 0.f;
    __syncthreads();
    for (int idx = tid; idx < 4 * 80 * 63; idx += 256)
        mel_s[(idx / 63) * 68 + (idx % 63) + 1] = mel[idx];
    bool valid[4];
#pragma unroll
    for (int v = 0; v < 4; v++) {
        int kk = 400 + p + 256 * (v - 2);
        valid[v] = (kk >= 0) && (kk < 800);
        if (valid[v])
            for (int idx = tid; idx < 6400; idx += 256)
                ws[(v * 80 + idx / 80) * 80 + idx % 80] = w_up[((idx / 80) * 80 + idx % 80) * 800 + kk];
    }
    __syncthreads();

    for (int tile = tid; tile < 320; tile += 256) {
        int og = tile >> 5, b = (tile >> 3) & 3, ug = tile & 7;
        int o0 = og * 8, u0 = ug * 8;
        float acc[8][8];
#pragma unroll
        for (int a = 0; a < 8; a++)
#pragma unroll
            for (int c = 0; c < 8; c++) acc[a][c] = 0.f;
        const float* msb = mel_s + b * 80 * 68;
#pragma unroll
        for (int v = 0; v < 4; v++) {
            if (!valid[v]) continue;
            int vv = v - 2;
#pragma unroll 4
            for (int m = 0; m < 80; m++) {
                const float* wr = ws + (v * 80 + m) * 80 + o0;
                float4 wA = *(const float4*)wr;
                float4 wB = *(const float4*)(wr + 4);
                float wv[8] = {wA.x, wA.y, wA.z, wA.w, wB.x, wB.y, wB.z, wB.w};
                const float* xr = msb + m * 68 + (u0 - vv) + 1;
                float xv[8];
#pragma unroll
                for (int c = 0; c < 8; c++) xv[c] = xr[c];
#pragma unroll
                for (int a = 0; a < 8; a++)
#pragma unroll
                    for (int c = 0; c < 8; c++)
                        acc[a][c] = fmaf(wv[a], xv[c], acc[a][c]);
            }
        }
#pragma unroll
        for (int a = 0; a < 8; a++) {
            float bo = b_up[o0 + a];
#pragma unroll
            for (int c = 0; c < 8; c++)
                if (u0 + c < 62)
                    g_cond[((size_t)b * 80 + o0 + a) * L_LEN + 256 * (u0 + c) + p] = acc[a][c] + bo;
        }
    }
}

// ---------------- fused residual block (mma.sync fp16 2-term) ----------------
#define XHI 0
#define ZHI 44032
#define SMEM_BLOCK 61440

__global__ void __launch_bounds__(512, 1) block_kernel(const float* __restrict__ bsk_all,
                                                       const float* __restrict__ brs_all,
                                                       int blk, int d, int first, int parity)
{
    char* smb = dynsmem;
    const uint32_t su = smem_u32(smb);
    const int tid = threadIdx.x, w = tid >> 5, lane = tid & 31;
    const int wr = w >> 1, wt = w & 1;
    const int b = blockIdx.y, t0 = blockIdx.x << 6;

    const float* res_in  = (parity ? g_res1 : g_res0) + (size_t)b * 120 * L_LEN;
    float*       res_out = (parity ? g_res0 : g_res1) + (size_t)b * 120 * L_LEN;
    const float* condb   = g_cond + (size_t)b * 80 * L_LEN;

    const uint4* A1 = ((const uint4*)g_W1f) + (size_t)blk * (20 * 16 * 2 * 32);
    const uint4* A2 = ((const uint4*)g_W2f) + (size_t)blk * (8 * 24 * 2 * 32);

    // stage X: [64t][320k] fp32 -> fp16
    __half* xh = (__half*)(smb + XHI);
    for (int idx = tid; idx < 320 * 64; idx += 512) {
        int t = idx & 63, k = idx >> 6;
        float v;
        if (k < 120)      { int ts = t0 + t - d; v = (ts >= 0) ? res_in[k * L_LEN + ts] : 0.f; }
        else if (k < 240)   v = res_in[(k - 120) * L_LEN + t0 + t];
        else                v = condb[(k - 240) * L_LEN + t0 + t];
        xh[t * 344 + k] = __float2half_rn(v);
    }
    __syncthreads();

    float acc[2][4][4];
#pragma unroll
    for (int m = 0; m < 2; m++)
#pragma unroll
        for (int n = 0; n < 4; n++)
#pragma unroll
            for (int q = 0; q < 4; q++) acc[m][n][q] = 0.f;

    const int brow = ((lane & 16) >> 1) + (lane & 7);

    // GEMM1: 20 chunks (W hi then W lo), register-double-buffered A, no barriers
    uint4 curA[2][2], nxtA[2][2];
#pragma unroll
    for (int m = 0; m < 2; m++)
#pragma unroll
        for (int j = 0; j < 2; j++)
            curA[m][j] = A1[(((2 * wr + m) * 2) + j) * 32 + lane];

    int kc = 0;
    for (int c2 = 0; c2 < 20; c2++) {
        if (c2 < 19) {
#pragma unroll
            for (int m = 0; m < 2; m++)
#pragma unroll
                for (int j = 0; j < 2; j++)
                    nxtA[m][j] = A1[((((c2 + 1) * 16 + (2 * wr + m)) * 2) + j) * 32 + lane];
        }
        const uint32_t xb = su + XHI;
#pragma unroll
        for (int j = 0; j < 2; j++) {
            uint32_t bf[2][4];
            const int bcol = (kc << 5) + j * 16 + (lane & 8);
#pragma unroll
            for (int np = 0; np < 2; np++)
                ldmB(bf[np], xb + (((wt << 5) + (np << 4) + brow) * 344 + bcol) * 2);
#pragma unroll
            for (int m = 0; m < 2; m++)
#pragma unroll
                for (int nt = 0; nt < 4; nt++)
                    mma16816(acc[m][nt], (const uint32_t*)&curA[m][j], &bf[nt >> 1][(nt & 1) << 1]);
        }
#pragma unroll
        for (int m = 0; m < 2; m++)
#pragma unroll
            for (int j = 0; j < 2; j++)
                curA[m][j] = nxtA[m][j];
        if (++kc == 10) kc = 0;
    }

    // activation -> z (fp16) [64t][136ch]
    const float* bg = g_bg + blk * 240;
    __half* zh = (__half*)(smb + ZHI);
#pragma unroll
    for (int m = 0; m < 2; m++) {
        int mt = 2 * wr + m;
        int ch = (mt << 3) + (lane >> 2);
        bool valid = ch < 120;
        float bf_ = valid ? bg[ch] : 0.f;
        float bg_ = valid ? bg[120 + ch] : 0.f;
#pragma unroll
        for (int nt = 0; nt < 4; nt++) {
            int tt = (wt << 5) + (nt << 3) + ((lane & 3) << 1);
#pragma unroll
            for (int q = 0; q < 2; q++) {
                float z = 0.f;
                if (valid) {
                    float f = acc[m][nt][q] + bf_;
                    float g = acc[m][nt][2 + q] + bg_;
                    z = tanhf_acc(f) * sigmoidf_(g);
                }
                zh[(tt + q) * 136 + ch] = __float2half_rn(z);
            }
        }
    }
    __syncthreads();

    float ac2[3][4][4];
#pragma unroll
    for (int m = 0; m < 3; m++)
#pragma unroll
        for (int n = 0; n < 4; n++)
#pragma unroll
            for (int q = 0; q < 4; q++) ac2[m][n][q] = 0.f;

    // GEMM2: 8 chunks, A fragments from L2 per chunk, no barriers
    for (int c2 = 0; c2 < 8; c2++) {
        uint4 a2[3][2];
#pragma unroll
        for (int m = 0; m < 3; m++)
#pragma unroll
            for (int j = 0; j < 2; j++)
                a2[m][j] = A2[(((c2 * 24 + (3 * wr + m)) * 2) + j) * 32 + lane];
        const uint32_t zb = su + ZHI;
#pragma unroll
        for (int j = 0; j < 2; j++) {
            uint32_t bf[2][4];
            const int bcol = ((c2 & 3) << 5) + j * 16 + (lane & 8);
#pragma unroll
            for (int np = 0; np < 2; np++)
                ldmB(bf[np], zb + (((wt << 5) + (np << 4) + brow) * 136 + bcol) * 2);
#pragma unroll
            for (int m = 0; m < 3; m++)
#pragma unroll
                for (int nt = 0; nt < 4; nt++)
                    mma16816(ac2[m][nt], (const uint32_t*)&a2[m][j], &bf[nt >> 1][(nt & 1) << 1]);
        }
    }

    const float* bsk = bsk_all + blk * 240;
    const float* brs = brs_all + blk * 120;
    float* skipb = g_skip + (size_t)b * 240 * L_LEN;
#pragma unroll
    for (int m = 0; m < 3; m++) {
        int mt = 3 * wr + m;
#pragma unroll
        for (int h2 = 0; h2 < 2; h2++) {
            int row = (mt << 4) + (lane >> 2) + (h2 << 3);
#pragma unroll
            for (int nt = 0; nt < 4; nt++) {
                int tt = t0 + (wt << 5) + (nt << 3) + ((lane & 3) << 1);
                float v0 = ac2[m][nt][h2 << 1], v1 = ac2[m][nt][(h2 << 1) + 1];
                if (row < 240) {
                    size_t o = (size_t)row * L_LEN + tt;
                    float bb = bsk[row];
                    if (first) { skipb[o] = v0 + bb; skipb[o + 1] = v1 + bb; }
                    else       { skipb[o] += v0 + bb; skipb[o + 1] += v1 + bb; }
                } else if (row >= 256 && row < 376) {
                    int rc = row - 256;
                    size_t o = (size_t)rc * L_LEN + tt;
                    float bb = brs[rc];
                    res_out[o]     = res_in[o]     + v0 + bb;
                    res_out[o + 1] = res_in[o + 1] + v1 + bb;
                }
            }
        }
    }
}

// ---------------- head GEMM (mma.sync fp16 2-term) ----------------
#define HXHI 0
#define SMEM_HEAD 33792

__global__ void __launch_bounds__(512, 1) head_kernel(const float* __restrict__ bias,
                                                      float* __restrict__ outp, int which)
{
    char* smb = dynsmem;
    const uint32_t su = smem_u32(smb);
    const int tid = threadIdx.x, w = tid >> 5, lane = tid & 31;
    const int wr = w >> 1, wt = w & 1;
    const int b = blockIdx.y, t0 = blockIdx.x << 6;

    const int Kreal = which ? 256 : 240;
    const float* srcb = (which ? g_h : g_skip) + (size_t)b * Kreal * L_LEN;
    const uint4* A = (const uint4*)(which ? g_WH2f : g_WH1f);
    float* out = (which ? outp : g_h) + (size_t)b * 256 * L_LEN;

    __half* xh = (__half*)(smb + HXHI);
    for (int idx = tid; idx < 256 * 64; idx += 512) {
        int t = idx & 63, k = idx >> 6;
        float v = (k < Kreal) ? srcb[k * L_LEN + t0 + t] : 0.f;
        v = v > 0.f ? v : 0.f;
        xh[t * 264 + k] = __float2half_rn(v);
    }
    __syncthreads();

    float acc[2][4][4];
#pragma unroll
    for (int m = 0; m < 2; m++)
#pragma unroll
        for (int n = 0; n < 4; n++)
#pragma unroll
            for (int q = 0; q < 4; q++) acc[m][n][q] = 0.f;

    const int brow = ((lane & 16) >> 1) + (lane & 7);

    uint4 curA[2][2], nxtA[2][2];
#pragma unroll
    for (int m = 0; m < 2; m++)
#pragma unroll
        for (int j = 0; j < 2; j++)
            curA[m][j] = A[(((2 * wr + m) * 2) + j) * 32 + lane];

    for (int c2 = 0; c2 < 16; c2++) {
        if (c2 < 15) {
#pragma unroll
            for (int m = 0; m < 2; m++)
#pragma unroll
                for (int j = 0; j < 2; j++)
                    nxtA[m][j] = A[((((c2 + 1) * 16 + (2 * wr + m)) * 2) + j) * 32 + lane];
        }
        const uint32_t xb = su + HXHI;
#pragma unroll
        for (int j = 0; j < 2; j++) {
            uint32_t bf[2][4];
            const int bcol = ((c2 & 7) << 5) + j * 16 + (lane & 8);
#pragma unroll
            for (int np = 0; np < 2; np++)
                ldmB(bf[np], xb + (((wt << 5) + (np << 4) + brow) * 264 + bcol) * 2);
#pragma unroll
            for (int m = 0; m < 2; m++)
#pragma unroll
                for (int nt = 0; nt < 4; nt++)
                    mma16816(acc[m][nt], (const uint32_t*)&curA[m][j], &bf[nt >> 1][(nt & 1) << 1]);
        }
#pragma unroll
        for (int m = 0; m < 2; m++)
#pragma unroll
            for (int j = 0; j < 2; j++)
                curA[m][j] = nxtA[m][j];
    }

#pragma unroll
    for (int m = 0; m < 2; m++) {
        int mt = 2 * wr + m;
#pragma unroll
        for (int h2 = 0; h2 < 2; h2++) {
            int ch = (mt << 4) + (lane >> 2) + (h2 << 3);
            float bb = bias[ch];
#pragma unroll
            for (int nt = 0; nt < 4; nt++) {
                int tt = t0 + (wt << 5) + (nt << 3) + ((lane & 3) << 1);
                size_t o = (size_t)ch * L_LEN + tt;
                out[o]     = acc[m][nt][h2 << 1] + bb;
                out[o + 1] = acc[m][nt][(h2 << 1) + 1] + bb;
            }
        }
    }
}

// ---------------- launcher ----------------
extern "C" void kernel_launch(void* const* d_in, const int* in_sizes, int n_in,
                              void* d_out, int out_size)
{
    const float* wav    = (const float*)d_in[0];
    const float* mel    = (const float*)d_in[1];
    const float* w_up   = (const float*)d_in[2];
    const float* b_up   = (const float*)d_in[3];
    const float* w_in   = (const float*)d_in[4];
    const float* b_in   = (const float*)d_in[5];
    const float* w_gate = (const float*)d_in[6];
    const float* b_gate = (const float*)d_in[7];
    const float* w_cond = (const float*)d_in[8];
    const float* b_cond = (const float*)d_in[9];
    const float* w_res  = (const float*)d_in[10];
    const float* b_res  = (const float*)d_in[11];
    const float* w_skip = (const float*)d_in[12];
    const float* b_skip = (const float*)d_in[13];
    const float* w_h1   = (const float*)d_in[14];
    const float* b_h1   = (const float*)d_in[15];
    const float* w_h2   = (const float*)d_in[16];
    const float* b_h2   = (const float*)d_in[17];
    float* out = (float*)d_out;

    const int SMEM_UP = (4 * 80 * 68 + 4 * 80 * 80) * 4;
    cudaFuncSetAttribute(block_kernel,    cudaFuncAttributeMaxDynamicSharedMemorySize, SMEM_BLOCK);
    cudaFuncSetAttribute(head_kernel,     cudaFuncAttributeMaxDynamicSharedMemorySize, SMEM_HEAD);
    cudaFuncSetAttribute(upsample_kernel, cudaFuncAttributeMaxDynamicSharedMemorySize, SMEM_UP);

    prep_kernel<<<4096, 256>>>(w_gate, b_gate, w_cond, b_cond, w_res, w_skip, w_h1, w_h2);
    upsample_kernel<<<256, 256, SMEM_UP>>>(mel, w_up, b_up);
    init_kernel<<<4096, 256>>>(wav, w_in, b_in);

    dim3 grid(NT64, 4);
    for (int i = 0; i < 16; i++)
        block_kernel<<<grid, 512, SMEM_BLOCK>>>(b_skip, b_res, i, 1 << (i & 7),
                                                (i == 0) ? 1 : 0, i & 1);

    head_kernel<<<grid, 512, SMEM_HEAD>>>(b_h1, out, 0);
    head_kernel<<<grid, 512, SMEM_HEAD>>>(b_h2, out, 1);
}